// round 1
// baseline (speedup 1.0000x reference)
#include <cuda_runtime.h>
#include <math.h>

// Problem constants (fixed by reference)
#define R_NODES 10
#define HID 128
#define HEADS 4
#define NE 36
#define B_DIM 16
#define T_DIM 800
#define BT (B_DIM * T_DIM)            // 12800 graph instances
#define NODE_F (R_NODES * HID)        // 1280 floats per instance
#define NTOT (BT * NODE_F)            // 16,384,000 floats
#define LN_EPS 1e-5f

// Ping-pong node-feature buffers (device globals: no allocation)
__device__ float g_nf0[NTOT];
__device__ float g_nf1[NTOT];

// Hardcoded graph CSR by destination node (deterministic from reference _build_edges):
// edges e0..e25 = 13 undirected pairs expanded both ways, e26..e35 = self loops.
__constant__ int c_start[R_NODES + 1] = {0, 5, 8, 12, 15, 17, 22, 27, 31, 33, 36};
__constant__ int c_src[NE] = {
    9, 5, 6, 1, 0,      // dst 0
    0, 2, 1,            // dst 1
    5, 1, 3, 2,         // dst 2
    2, 4, 3,            // dst 3
    3, 4,               // dst 4
    6, 2, 0, 7, 5,      // dst 5
    5, 9, 0, 7, 6,      // dst 6
    6, 5, 8, 7,         // dst 7
    7, 8,               // dst 8
    6, 0, 9             // dst 9
};

__device__ __forceinline__ float gelu_exact(float v) {
    return 0.5f * v * (1.0f + erff(v * 0.70710678118654752440f));
}

// ---------------------------------------------------------------------------
// Encoder: per-region Linear(6->128) + LayerNorm(128) + GELU.
// 256 threads / block, 2 instances / block. Warp-local LayerNorm (no smem).
// ---------------------------------------------------------------------------
__global__ void __launch_bounds__(256) encoder_kernel(
    const float* __restrict__ x,      // (BT, 60)
    const float* __restrict__ Wenc,   // (R, 6, 128)
    const float* __restrict__ benc,   // (R, 128)
    const float* __restrict__ gamma,  // (R, 128)
    const float* __restrict__ beta,   // (R, 128)
    float* __restrict__ nf_out,       // (BT, R, 128)
    float* __restrict__ region_out)   // may be null
{
    const int tid  = threadIdx.x;
    const int lane = tid & 31;
    const int w4   = (tid >> 5) & 3;          // warp within half-block
    const int inst = tid >> 7;                // 0 or 1
    const long bt  = (long)blockIdx.x * 2 + inst;
    const float* xr = x + bt * (R_NODES * 6);
    float* outp = nf_out + bt * NODE_F;
    float* regp = region_out ? region_out + bt * NODE_F : nullptr;

    for (int r = w4; r < R_NODES; r += 4) {
        float xv[6];
#pragma unroll
        for (int c = 0; c < 6; ++c) xv[c] = xr[r * 6 + c];

        float h[4];
#pragma unroll
        for (int j = 0; j < 4; ++j) {
            int k = lane + 32 * j;
            float a = benc[r * HID + k];
#pragma unroll
            for (int c = 0; c < 6; ++c)
                a = fmaf(xv[c], Wenc[(r * 6 + c) * HID + k], a);
            h[j] = a;
        }
        float s  = h[0] + h[1] + h[2] + h[3];
        float sq = h[0]*h[0] + h[1]*h[1] + h[2]*h[2] + h[3]*h[3];
#pragma unroll
        for (int o = 16; o > 0; o >>= 1) {
            s  += __shfl_xor_sync(0xffffffffu, s,  o);
            sq += __shfl_xor_sync(0xffffffffu, sq, o);
        }
        float mean = s * (1.0f / 128.0f);
        float var  = sq * (1.0f / 128.0f) - mean * mean;
        float rstd = rsqrtf(var + LN_EPS);
#pragma unroll
        for (int j = 0; j < 4; ++j) {
            int k = lane + 32 * j;
            float v = (h[j] - mean) * rstd * gamma[r * HID + k] + beta[r * HID + k];
            float g = gelu_exact(v);
            outp[r * HID + k] = g;
            if (regp) regp[r * HID + k] = g;
        }
    }
}

// ---------------------------------------------------------------------------
// Fused GAT layer. One CTA = 2 graph instances, 256 threads.
// Phases: load nf -> GEMM xp (smem) -> attention dots -> segment softmax
//         -> weighted aggregation + head-mean + bias + GELU + residual.
// ---------------------------------------------------------------------------
#define SM_NF    0                      // 2*10*128 = 2560 floats
#define SM_XP    2560                   // 2*10*512 = 10240 floats
#define SM_ATT   12800                  // 2*4*128  = 1024 floats (asrc, adst)
#define SM_AL    13824                  // 2*2*10*4 = 160 floats
#define SM_ALPHA 13984                  // 2*36*4   = 288 floats
#define SM_FLOATS 14272
#define SM_BYTES (SM_FLOATS * 4)

__global__ void __launch_bounds__(256) gat_kernel(
    const float* __restrict__ nf_in,  // (BT, 1280)
    const float* __restrict__ W,      // (128, 512) for this layer
    const float* __restrict__ asrc,   // (4, 128)
    const float* __restrict__ adst,   // (4, 128)
    const float* __restrict__ bg,     // (128,)
    float* __restrict__ nf_out)       // (BT, 1280)
{
    extern __shared__ float sm[];
    float* s_nf    = sm + SM_NF;
    float* s_xp    = sm + SM_XP;
    float* s_att   = sm + SM_ATT;
    float* s_al    = sm + SM_AL;
    float* s_alpha = sm + SM_ALPHA;

    const int tid = threadIdx.x;
    const long base = (long)blockIdx.x * 2 * NODE_F;

    // Load 2 instances of nf + attention vectors
#pragma unroll
    for (int i = tid; i < 2 * NODE_F; i += 256) s_nf[i] = nf_in[base + i];
#pragma unroll
    for (int i = tid; i < 512; i += 256) {
        s_att[i]       = asrc[i];
        s_att[512 + i] = adst[i];
    }
    __syncthreads();

    // ---- GEMM: xp[inst][n][col] = sum_f nf[inst][n][f] * W[f][col] ----
    // Thread owns cols c0 = tid, c1 = tid + 256 for all 20 (inst, node) rows.
    const int c0 = tid, c1 = tid + 256;
    float acc[2][R_NODES][2];
#pragma unroll
    for (int i = 0; i < 2; ++i)
#pragma unroll
        for (int n = 0; n < R_NODES; ++n) { acc[i][n][0] = 0.f; acc[i][n][1] = 0.f; }

    const float4* nf4 = reinterpret_cast<const float4*>(s_nf);
    for (int f4 = 0; f4 < 32; ++f4) {
        const float* wp = W + f4 * 4 * 512;
        float w00 = wp[c0],          w01 = wp[c1];
        float w10 = wp[512 + c0],    w11 = wp[512 + c1];
        float w20 = wp[1024 + c0],   w21 = wp[1024 + c1];
        float w30 = wp[1536 + c0],   w31 = wp[1536 + c1];
#pragma unroll
        for (int i = 0; i < 2; ++i) {
#pragma unroll
            for (int n = 0; n < R_NODES; ++n) {
                float4 v = nf4[(i * R_NODES + n) * 32 + f4];
                acc[i][n][0] = fmaf(v.x, w00, fmaf(v.y, w10, fmaf(v.z, w20, fmaf(v.w, w30, acc[i][n][0]))));
                acc[i][n][1] = fmaf(v.x, w01, fmaf(v.y, w11, fmaf(v.z, w21, fmaf(v.w, w31, acc[i][n][1]))));
            }
        }
    }
#pragma unroll
    for (int i = 0; i < 2; ++i)
#pragma unroll
        for (int n = 0; n < R_NODES; ++n) {
            s_xp[(i * R_NODES + n) * 512 + c0] = acc[i][n][0];
            s_xp[(i * R_NODES + n) * 512 + c1] = acc[i][n][1];
        }
    __syncthreads();

    // ---- Attention logits: al[inst][sd][n][h] = <xp[inst][n][h], a_sd[h]> ----
    // 160 warp-cooperative dot products of length 128 over 8 warps.
    const int warp = tid >> 5, lane = tid & 31;
    for (int cid = warp; cid < 160; cid += 8) {
        int inst = cid / 80;
        int sd   = (cid % 80) / 40;
        int n    = (cid % 40) >> 2;
        int h    = cid & 3;
        const float* xv = s_xp + (inst * R_NODES + n) * 512 + h * HID;
        const float* av = s_att + sd * 512 + h * HID;
        float d = xv[lane]      * av[lane]
                + xv[lane + 32] * av[lane + 32]
                + xv[lane + 64] * av[lane + 64]
                + xv[lane + 96] * av[lane + 96];
#pragma unroll
        for (int o = 16; o > 0; o >>= 1) d += __shfl_xor_sync(0xffffffffu, d, o);
        if (lane == 0) s_al[((inst * 2 + sd) * R_NODES + n) * 4 + h] = d;
    }
    __syncthreads();

    // ---- Segment softmax over incoming edges, per (inst, dst node, head) ----
    if (tid < 80) {
        int inst = tid / 40;
        int n    = (tid % 40) >> 2;
        int h    = tid & 3;
        float ald = s_al[((inst * 2 + 1) * R_NODES + n) * 4 + h];
        int s0 = c_start[n], s1 = c_start[n + 1];
        float vbuf[5];
        float m = -1e30f;
        for (int k = s0; k < s1; ++k) {
            float v = s_al[((inst * 2 + 0) * R_NODES + c_src[k]) * 4 + h] + ald;
            v = v > 0.f ? v : 0.2f * v;   // leaky_relu(0.2)
            vbuf[k - s0] = v;
            m = fmaxf(m, v);
        }
        float ssum = 0.f;
        for (int k = s0; k < s1; ++k) {
            float ex = expf(vbuf[k - s0] - m);
            ssum += ex;
            s_alpha[(inst * NE + k) * 4 + h] = ex;
        }
        float inv = 1.0f / ssum;
        for (int k = s0; k < s1; ++k) s_alpha[(inst * NE + k) * 4 + h] *= inv;
    }
    __syncthreads();

    // ---- Aggregate: out[n][f] = mean_h sum_{e->n} alpha[e][h]*xp[src][h][f] ----
    for (int idx = tid; idx < 2 * NODE_F; idx += 256) {
        int inst = idx / NODE_F;
        int rem  = idx % NODE_F;
        int n    = rem >> 7;
        int f    = rem & 127;
        int s0 = c_start[n], s1 = c_start[n + 1];
        float a = 0.f;
        for (int k = s0; k < s1; ++k) {
            const float* xv = s_xp + (inst * R_NODES + c_src[k]) * 512 + f;
            const float* al = s_alpha + (inst * NE + k) * 4;
            a = fmaf(al[0], xv[0],
                fmaf(al[1], xv[HID],
                fmaf(al[2], xv[2 * HID],
                fmaf(al[3], xv[3 * HID], a))));
        }
        float o = 0.25f * a + bg[f];                 // mean over 4 heads + bias
        nf_out[base + idx] = gelu_exact(o) + s_nf[idx];  // gelu + residual
    }
}

// ---------------------------------------------------------------------------
extern "C" void kernel_launch(void* const* d_in, const int* in_sizes, int n_in,
                              void* d_out, int out_size)
{
    const float* x     = (const float*)d_in[0];
    const float* Wenc  = (const float*)d_in[1];
    const float* benc  = (const float*)d_in[2];
    const float* gamma = (const float*)d_in[3];
    const float* beta  = (const float*)d_in[4];
    const float* Wg    = (const float*)d_in[5];   // (3, 128, 512)
    const float* asrc  = (const float*)d_in[6];   // (3, 4, 128)
    const float* adst  = (const float*)d_in[7];
    const float* bg    = (const float*)d_in[8];   // (3, 128)
    // d_in[9], d_in[10] = src/dst edge lists: graph is static, CSR hardcoded.

    float* out = (float*)d_out;
    float* region_out = (out_size >= 2 * NTOT) ? out + NTOT : nullptr;

    float* nf0;  cudaGetSymbolAddress((void**)&nf0, g_nf0);
    float* nf1;  cudaGetSymbolAddress((void**)&nf1, g_nf1);

    cudaFuncSetAttribute(gat_kernel, cudaFuncAttributeMaxDynamicSharedMemorySize, SM_BYTES);

    const int grid = BT / 2;   // 6400 blocks, 2 instances each

    encoder_kernel<<<grid, 256>>>(x, Wenc, benc, gamma, beta, nf0, region_out);

    // Layer 0: nf0 -> nf1
    gat_kernel<<<grid, 256, SM_BYTES>>>(nf0, Wg,              asrc,        adst,        bg,       nf1);
    // Layer 1: nf1 -> nf0
    gat_kernel<<<grid, 256, SM_BYTES>>>(nf1, Wg + 128 * 512,  asrc + 512,  adst + 512,  bg + 128, nf0);
    // Layer 2: nf0 -> graph_features (d_out offset 0)
    gat_kernel<<<grid, 256, SM_BYTES>>>(nf0, Wg + 2*128*512,  asrc + 1024, adst + 1024, bg + 256, out);
}

// round 3
// speedup vs baseline: 1.2399x; 1.2399x over previous
#include <cuda_runtime.h>
#include <cuda_bf16.h>
#include <math.h>
#include <stdint.h>

// Problem constants
#define R_NODES 10
#define HID 128
#define NE 36
#define BT 12800                       // 16*800 graph instances
#define NODE_F 1280
#define NTOT (BT * NODE_F)
#define LN_EPS 1e-5f
#define NI 8                           // instances per GAT CTA
#define ROWS 80                        // NI * R_NODES
#define GRID_GAT (BT / NI)             // 1600

// Ping-pong node-feature buffers
__device__ float g_nf0[NTOT];
__device__ float g_nf1[NTOT];
// Pre-split, pre-swizzled W^T tiles: [layer][head]{hi 32KB, lo 32KB}
__device__ __align__(16) uint8_t g_Wt[3 * 4 * 65536];

// Static graph CSR by destination
__constant__ int c_start[R_NODES + 1] = {0, 5, 8, 12, 15, 17, 22, 27, 31, 33, 36};
__constant__ int c_src[NE] = {
    9, 5, 6, 1, 0,   0, 2, 1,   5, 1, 3, 2,   2, 4, 3,   3, 4,
    6, 2, 0, 7, 5,   5, 9, 0, 7, 6,   6, 5, 8, 7,   7, 8,   6, 0, 9
};

__device__ __forceinline__ float gelu_exact(float v) {
    return 0.5f * v * (1.0f + erff(v * 0.70710678118654752440f));
}
__device__ __forceinline__ uint32_t smem_u32(const void* p) {
    uint32_t a;
    asm("{ .reg .u64 t; cvta.to.shared.u64 t, %1; cvt.u32.u64 %0, t; }" : "=r"(a) : "l"(p));
    return a;
}
__device__ __forceinline__ void ldsm_x4(uint32_t* r, uint32_t addr) {
    asm volatile("ldmatrix.sync.aligned.m8n8.x4.shared.b16 {%0,%1,%2,%3}, [%4];"
                 : "=r"(r[0]), "=r"(r[1]), "=r"(r[2]), "=r"(r[3]) : "r"(addr));
}
__device__ __forceinline__ void mma_bf16(float* d, const uint32_t* a, uint32_t b0, uint32_t b1) {
    asm volatile("mma.sync.aligned.m16n8k16.row.col.f32.bf16.bf16.f32 "
                 "{%0,%1,%2,%3}, {%4,%5,%6,%7}, {%8,%9}, {%0,%1,%2,%3};"
                 : "+f"(d[0]), "+f"(d[1]), "+f"(d[2]), "+f"(d[3])
                 : "r"(a[0]), "r"(a[1]), "r"(a[2]), "r"(a[3]), "r"(b0), "r"(b1));
}
__device__ __forceinline__ void cpa16(uint32_t saddr, const void* g) {
    asm volatile("cp.async.cg.shared.global [%0], [%1], 16;" :: "r"(saddr), "l"(g) : "memory");
}
__device__ __forceinline__ void split_bf16x2(float v0, float v1, uint32_t& hi, uint32_t& lo) {
    __nv_bfloat16 h0 = __float2bfloat16(v0);
    __nv_bfloat16 h1 = __float2bfloat16(v1);
    __nv_bfloat16 l0 = __float2bfloat16(v0 - __bfloat162float(h0));
    __nv_bfloat16 l1 = __float2bfloat16(v1 - __bfloat162float(h1));
    hi = (uint32_t)__bfloat16_as_ushort(h0) | ((uint32_t)__bfloat16_as_ushort(h1) << 16);
    lo = (uint32_t)__bfloat16_as_ushort(l0) | ((uint32_t)__bfloat16_as_ushort(l1) << 16);
}

// ---------------------------------------------------------------------------
// W prep: Wg (L,128,512) -> W^T bf16 hi/lo, [n=128 rows][k=128], xor-swizzled:
// byte(n,k) = n*256 + ((k>>3) ^ (n&7))*16 + (k&7)*2
// ---------------------------------------------------------------------------
__global__ void wt_kernel(const float* __restrict__ Wg) {
    int l = blockIdx.x >> 2, h = blockIdx.x & 3;
    uint8_t* hi = g_Wt + (size_t)(l * 4 + h) * 65536;
    uint8_t* lo = hi + 32768;
    for (int idx = threadIdx.x; idx < 128 * 128; idx += 256) {
        int n = idx >> 7, k = idx & 127;
        float w = Wg[l * 65536 + k * 512 + h * 128 + n];
        __nv_bfloat16 wh = __float2bfloat16(w);
        __nv_bfloat16 wl = __float2bfloat16(w - __bfloat162float(wh));
        uint32_t off = (uint32_t)(n * 256 + (((k >> 3) ^ (n & 7)) * 16) + (k & 7) * 2);
        *(__nv_bfloat16*)(hi + off) = wh;
        *(__nv_bfloat16*)(lo + off) = wl;
    }
}

// ---------------------------------------------------------------------------
// Encoder (unchanged from round 1)
// ---------------------------------------------------------------------------
__global__ void __launch_bounds__(256) encoder_kernel(
    const float* __restrict__ x, const float* __restrict__ Wenc,
    const float* __restrict__ benc, const float* __restrict__ gamma,
    const float* __restrict__ beta, float* __restrict__ nf_out,
    float* __restrict__ region_out)
{
    const int tid = threadIdx.x;
    const int lane = tid & 31;
    const int w4 = (tid >> 5) & 3;
    const int inst = tid >> 7;
    const long bt = (long)blockIdx.x * 2 + inst;
    const float* xr = x + bt * (R_NODES * 6);
    float* outp = nf_out + bt * NODE_F;
    float* regp = region_out ? region_out + bt * NODE_F : nullptr;

    for (int r = w4; r < R_NODES; r += 4) {
        float xv[6];
#pragma unroll
        for (int c = 0; c < 6; ++c) xv[c] = xr[r * 6 + c];
        float h[4];
#pragma unroll
        for (int j = 0; j < 4; ++j) {
            int k = lane + 32 * j;
            float a = benc[r * HID + k];
#pragma unroll
            for (int c = 0; c < 6; ++c) a = fmaf(xv[c], Wenc[(r * 6 + c) * HID + k], a);
            h[j] = a;
        }
        float s = h[0] + h[1] + h[2] + h[3];
        float sq = h[0]*h[0] + h[1]*h[1] + h[2]*h[2] + h[3]*h[3];
#pragma unroll
        for (int o = 16; o > 0; o >>= 1) {
            s  += __shfl_xor_sync(0xffffffffu, s, o);
            sq += __shfl_xor_sync(0xffffffffu, sq, o);
        }
        float mean = s * (1.0f / 128.0f);
        float var = sq * (1.0f / 128.0f) - mean * mean;
        float rstd = rsqrtf(var + LN_EPS);
#pragma unroll
        for (int j = 0; j < 4; ++j) {
            int k = lane + 32 * j;
            float v = (h[j] - mean) * rstd * gamma[r * HID + k] + beta[r * HID + k];
            float g = gelu_exact(v);
            outp[r * HID + k] = g;
            if (regp) regp[r * HID + k] = g;
        }
    }
}

// ---------------------------------------------------------------------------
// GAT layer, mma.sync bf16 split-3. CTA = 8 instances (80 rows, 5 m16-tiles),
// head-sequential (N=128/head), K=128. 256 threads.
// smem byte map:
//   0       A_hi (80*256 = 20480)
//   20480   A_lo (20480)
//   40960   B    (hi 32768 + lo 32768)
//   106496  xp   (80*132*4 = 42240 fp32, stride 132)
//   148736  out  (80*128*4 = 40960 fp32)
//   189696  att  (1024 fp32: asrc[4][128], adst[4][128])
//   193792  als  (80 f)   194112 ald (80 f)   194432 alpha (8*36 f)
// ---------------------------------------------------------------------------
#define A_LO_B   20480
#define B_B      40960
#define XP_B     106496
#define OUT_B    148736
#define ATT_B    189696
#define ALS_B    193792
#define ALD_B    194112
#define ALPHA_B  194432
#define SM_DYNBYTES 195584

__global__ void __launch_bounds__(256, 1) gat_mma_kernel(
    const float* __restrict__ nf_in, const uint8_t* __restrict__ Wt,
    const float* __restrict__ asrc, const float* __restrict__ adst,
    const float* __restrict__ bg, float* __restrict__ nf_out)
{
    extern __shared__ uint8_t smb[];
    const uint32_t sb = smem_u32(smb);
    float* s_xp    = (float*)(smb + XP_B);
    float* s_out   = (float*)(smb + OUT_B);
    float* s_att   = (float*)(smb + ATT_B);
    float* s_als   = (float*)(smb + ALS_B);
    float* s_ald   = (float*)(smb + ALD_B);
    float* s_alpha = (float*)(smb + ALPHA_B);

    const int tid  = threadIdx.x;
    const int wid  = tid >> 5;
    const int lane = tid & 31;
    const long blk = blockIdx.x;

    // Issue cp.async for head-0 B while we do the A conversion
    for (int i = tid; i < 4096; i += 256) cpa16(sb + B_B + i * 16, Wt + i * 16);
    asm volatile("cp.async.commit_group;" ::: "memory");

    // attention vectors
    for (int i = tid; i < 512; i += 256) {
        s_att[i]       = asrc[i];
        s_att[512 + i] = adst[i];
    }

    // A fill: 80 rows x 128 k -> bf16 hi/lo, swizzled (1280 chunk tasks of 8 floats)
#pragma unroll
    for (int it = 0; it < 5; ++it) {
        int t = tid + 256 * it;
        int r = t >> 4, kb = t & 15;
        const float* src = nf_in + (blk * NI + r / R_NODES) * NODE_F + (r % R_NODES) * HID + kb * 8;
        float4 a = *(const float4*)(src);
        float4 b = *(const float4*)(src + 4);
        uint32_t hi[4], lo[4];
        split_bf16x2(a.x, a.y, hi[0], lo[0]);
        split_bf16x2(a.z, a.w, hi[1], lo[1]);
        split_bf16x2(b.x, b.y, hi[2], lo[2]);
        split_bf16x2(b.z, b.w, hi[3], lo[3]);
        uint32_t off = (uint32_t)(r * 256 + ((kb ^ (r & 7)) * 16));
        *(uint4*)(smb + off)          = make_uint4(hi[0], hi[1], hi[2], hi[3]);
        *(uint4*)(smb + A_LO_B + off) = make_uint4(lo[0], lo[1], lo[2], lo[3]);
    }
    asm volatile("cp.async.wait_group 0;" ::: "memory");
    __syncthreads();

    const uint32_t sA = sb, sB = sb + B_B;

    for (int h = 0; h < 4; ++h) {
        // ---- GEMM: warp wid owns cols [wid*16, wid*16+16), all 5 m-tiles ----
        float acc[5][2][4];
#pragma unroll
        for (int mt = 0; mt < 5; ++mt)
#pragma unroll
            for (int nt = 0; nt < 2; ++nt)
#pragma unroll
                for (int j = 0; j < 4; ++j) acc[mt][nt][j] = 0.f;

#pragma unroll
        for (int kc = 0; kc < 8; ++kc) {
            uint32_t bh[4], bl[4];
            {
                int m = lane >> 3, i = lane & 7;
                int n = wid * 16 + (m >> 1) * 8 + i;
                int kb = kc * 2 + (m & 1);
                uint32_t addr = sB + (uint32_t)(n * 256 + ((kb ^ (n & 7)) * 16));
                ldsm_x4(bh, addr);
                ldsm_x4(bl, addr + 32768);
            }
            uint32_t ahi[5][4], alo[5][4];
            {
                int m = lane >> 3, i = lane & 7;
                int kb = kc * 2 + (m >> 1);
                int rbase = (m & 1) * 8 + i;
#pragma unroll
                for (int mt = 0; mt < 5; ++mt) {
                    int r = mt * 16 + rbase;
                    uint32_t addr = sA + (uint32_t)(r * 256 + ((kb ^ (r & 7)) * 16));
                    ldsm_x4(ahi[mt], addr);
                    ldsm_x4(alo[mt], addr + A_LO_B);
                }
            }
#pragma unroll
            for (int mt = 0; mt < 5; ++mt) {
                mma_bf16(acc[mt][0], ahi[mt], bh[0], bh[1]);
                mma_bf16(acc[mt][1], ahi[mt], bh[2], bh[3]);
                mma_bf16(acc[mt][0], alo[mt], bh[0], bh[1]);
                mma_bf16(acc[mt][1], alo[mt], bh[2], bh[3]);
                mma_bf16(acc[mt][0], ahi[mt], bl[0], bl[1]);
                mma_bf16(acc[mt][1], ahi[mt], bl[2], bl[3]);
            }
        }
        // write xp (stride 132)
#pragma unroll
        for (int mt = 0; mt < 5; ++mt)
#pragma unroll
            for (int nt = 0; nt < 2; ++nt) {
                int r0 = mt * 16 + (lane >> 2);
                int c  = wid * 16 + nt * 8 + (lane & 3) * 2;
                *(float2*)(s_xp + r0 * 132 + c)       = make_float2(acc[mt][nt][0], acc[mt][nt][1]);
                *(float2*)(s_xp + (r0 + 8) * 132 + c) = make_float2(acc[mt][nt][2], acc[mt][nt][3]);
            }
        __syncthreads();

        // prefetch next head's B (B no longer read until next GEMM)
        if (h < 3) {
            const uint8_t* gsrc = Wt + (size_t)(h + 1) * 65536;
            for (int i = tid; i < 4096; i += 256) cpa16(sb + B_B + i * 16, gsrc + i * 16);
            asm volatile("cp.async.commit_group;" ::: "memory");
        }

        // ---- logits: als/ald per row for this head ----
        {
#pragma unroll
            for (int rr = 0; rr < 10; ++rr) {
                int r = wid * 10 + rr;
                float as = 0.f, ad = 0.f;
#pragma unroll
                for (int j = 0; j < 4; ++j) {
                    float xv = s_xp[r * 132 + lane + 32 * j];
                    as = fmaf(xv, s_att[h * 128 + lane + 32 * j], as);
                    ad = fmaf(xv, s_att[512 + h * 128 + lane + 32 * j], ad);
                }
#pragma unroll
                for (int o = 16; o > 0; o >>= 1) {
                    as += __shfl_xor_sync(0xffffffffu, as, o);
                    ad += __shfl_xor_sync(0xffffffffu, ad, o);
                }
                if (lane == 0) { s_als[r] = as; s_ald[r] = ad; }
            }
        }
        __syncthreads();

        // ---- segment softmax for this head ----
        if (tid < 80) {
            int il = tid / 10, dst = tid % 10, rb = il * 10;
            float ald = s_ald[rb + dst];
            int s0 = c_start[dst], s1 = c_start[dst + 1];
            float vb[5], m = -1e30f;
            for (int k = s0; k < s1; ++k) {
                float v = s_als[rb + c_src[k]] + ald;
                v = v > 0.f ? v : 0.2f * v;
                vb[k - s0] = v;
                m = fmaxf(m, v);
            }
            float ssum = 0.f;
            for (int k = s0; k < s1; ++k) {
                float ex = expf(vb[k - s0] - m);
                ssum += ex;
                s_alpha[il * NE + k] = ex;
            }
            float inv = 1.0f / ssum;
            for (int k = s0; k < s1; ++k) s_alpha[il * NE + k] *= inv;
        }
        __syncthreads();

        // ---- aggregation for this head ----
#pragma unroll
        for (int it = 0; it < 10; ++it) {
            int q = tid + 256 * it;                 // 2560 float4 tasks
            int il = q / 320, rem = q % 320, dst = rem >> 5, f = (rem & 31) * 4;
            float4 a4;
            if (h == 0) { a4.x = a4.y = a4.z = a4.w = 0.f; }
            else          a4 = ((float4*)s_out)[q];
            int s0 = c_start[dst], s1 = c_start[dst + 1];
            for (int k = s0; k < s1; ++k) {
                int row = il * 10 + c_src[k];
                float al = s_alpha[il * NE + k];
                float4 xv = *(const float4*)(s_xp + row * 132 + f);
                a4.x = fmaf(al, xv.x, a4.x);
                a4.y = fmaf(al, xv.y, a4.y);
                a4.z = fmaf(al, xv.z, a4.z);
                a4.w = fmaf(al, xv.w, a4.w);
            }
            ((float4*)s_out)[q] = a4;
        }
        if (h < 3) asm volatile("cp.async.wait_group 0;" ::: "memory");
        __syncthreads();
    }

    // ---- epilogue: head mean + bias + GELU + residual ----
#pragma unroll
    for (int it = 0; it < 10; ++it) {
        int q = tid + 256 * it;
        int il = q / 320, rem = q % 320, dst = rem >> 5, f = (rem & 31) * 4;
        long ig = blk * NI + il;
        float4 o = ((float4*)s_out)[q];
        float4 bgv = *(const float4*)(bg + f);
        float4 rs  = *(const float4*)(nf_in + ig * NODE_F + dst * HID + f);
        float4 w;
        w.x = gelu_exact(fmaf(0.25f, o.x, bgv.x)) + rs.x;
        w.y = gelu_exact(fmaf(0.25f, o.y, bgv.y)) + rs.y;
        w.z = gelu_exact(fmaf(0.25f, o.z, bgv.z)) + rs.z;
        w.w = gelu_exact(fmaf(0.25f, o.w, bgv.w)) + rs.w;
        *(float4*)(nf_out + ig * NODE_F + dst * HID + f) = w;
    }
}

// ---------------------------------------------------------------------------
extern "C" void kernel_launch(void* const* d_in, const int* in_sizes, int n_in,
                              void* d_out, int out_size)
{
    const float* x     = (const float*)d_in[0];
    const float* Wenc  = (const float*)d_in[1];
    const float* benc  = (const float*)d_in[2];
    const float* gamma = (const float*)d_in[3];
    const float* beta  = (const float*)d_in[4];
    const float* Wg    = (const float*)d_in[5];
    const float* asrc  = (const float*)d_in[6];
    const float* adst  = (const float*)d_in[7];
    const float* bg    = (const float*)d_in[8];

    float* out = (float*)d_out;
    float* region_out = (out_size >= 2 * NTOT) ? out + NTOT : nullptr;

    float* nf0;  cudaGetSymbolAddress((void**)&nf0, g_nf0);
    float* nf1;  cudaGetSymbolAddress((void**)&nf1, g_nf1);
    uint8_t* wt; cudaGetSymbolAddress((void**)&wt, g_Wt);

    cudaFuncSetAttribute(gat_mma_kernel, cudaFuncAttributeMaxDynamicSharedMemorySize, SM_DYNBYTES);

    wt_kernel<<<12, 256>>>(Wg);
    encoder_kernel<<<BT / 2, 256>>>(x, Wenc, benc, gamma, beta, nf0, region_out);

    gat_mma_kernel<<<GRID_GAT, 256, SM_DYNBYTES>>>(nf0, wt,               asrc,        adst,        bg,       nf1);
    gat_mma_kernel<<<GRID_GAT, 256, SM_DYNBYTES>>>(nf1, wt + 4 * 65536,   asrc + 512,  adst + 512,  bg + 128, nf0);
    gat_mma_kernel<<<GRID_GAT, 256, SM_DYNBYTES>>>(nf0, wt + 8 * 65536,   asrc + 1024, adst + 1024, bg + 256, out);
}

// round 4
// speedup vs baseline: 1.4410x; 1.1622x over previous
#include <cuda_runtime.h>
#include <cuda_bf16.h>
#include <math.h>
#include <stdint.h>

// Problem constants
#define R_NODES 10
#define HID 128
#define NE 36
#define BT 12800
#define NODE_F 1280
#define NTOT (BT * NODE_F)
#define LN_EPS 1e-5f
#define NI 4                            // instances per GAT CTA
#define NROWS 40                        // NI * R_NODES
#define GRID_GAT (BT / NI)              // 3200

__device__ float g_nf0[NTOT];
__device__ float g_nf1[NTOT];
// Pre-split, pre-swizzled W^T tiles: [layer][head]{hi 32KB, lo 32KB}
__device__ __align__(16) uint8_t g_Wt[3 * 4 * 65536];

__constant__ int c_start[R_NODES + 1] = {0, 5, 8, 12, 15, 17, 22, 27, 31, 33, 36};
__constant__ int c_src[NE] = {
    9, 5, 6, 1, 0,   0, 2, 1,   5, 1, 3, 2,   2, 4, 3,   3, 4,
    6, 2, 0, 7, 5,   5, 9, 0, 7, 6,   6, 5, 8, 7,   7, 8,   6, 0, 9
};

__device__ __forceinline__ float gelu_exact(float v) {
    return 0.5f * v * (1.0f + erff(v * 0.70710678118654752440f));
}
__device__ __forceinline__ uint32_t smem_u32(const void* p) {
    uint32_t a;
    asm("{ .reg .u64 t; cvta.to.shared.u64 t, %1; cvt.u32.u64 %0, t; }" : "=r"(a) : "l"(p));
    return a;
}
__device__ __forceinline__ void ldsm_x4(uint32_t* r, uint32_t addr) {
    asm volatile("ldmatrix.sync.aligned.m8n8.x4.shared.b16 {%0,%1,%2,%3}, [%4];"
                 : "=r"(r[0]), "=r"(r[1]), "=r"(r[2]), "=r"(r[3]) : "r"(addr));
}
__device__ __forceinline__ void mma_bf16(float* d, const uint32_t* a, uint32_t b0, uint32_t b1) {
    asm volatile("mma.sync.aligned.m16n8k16.row.col.f32.bf16.bf16.f32 "
                 "{%0,%1,%2,%3}, {%4,%5,%6,%7}, {%8,%9}, {%0,%1,%2,%3};"
                 : "+f"(d[0]), "+f"(d[1]), "+f"(d[2]), "+f"(d[3])
                 : "r"(a[0]), "r"(a[1]), "r"(a[2]), "r"(a[3]), "r"(b0), "r"(b1));
}
__device__ __forceinline__ void cpa16(uint32_t saddr, const void* g) {
    asm volatile("cp.async.cg.shared.global [%0], [%1], 16;" :: "r"(saddr), "l"(g) : "memory");
}
__device__ __forceinline__ void split_bf16x2(float v0, float v1, uint32_t& hi, uint32_t& lo) {
    __nv_bfloat16 h0 = __float2bfloat16(v0);
    __nv_bfloat16 h1 = __float2bfloat16(v1);
    __nv_bfloat16 l0 = __float2bfloat16(v0 - __bfloat162float(h0));
    __nv_bfloat16 l1 = __float2bfloat16(v1 - __bfloat162float(h1));
    hi = (uint32_t)__bfloat16_as_ushort(h0) | ((uint32_t)__bfloat16_as_ushort(h1) << 16);
    lo = (uint32_t)__bfloat16_as_ushort(l0) | ((uint32_t)__bfloat16_as_ushort(l1) << 16);
}

// ---------------------------------------------------------------------------
// W prep (unchanged): W^T bf16 hi/lo, [n rows][k], xor-swizzled
// ---------------------------------------------------------------------------
__global__ void wt_kernel(const float* __restrict__ Wg) {
    int l = blockIdx.x >> 2, h = blockIdx.x & 3;
    uint8_t* hi = g_Wt + (size_t)(l * 4 + h) * 65536;
    uint8_t* lo = hi + 32768;
    for (int idx = threadIdx.x; idx < 128 * 128; idx += 256) {
        int n = idx >> 7, k = idx & 127;
        float w = Wg[l * 65536 + k * 512 + h * 128 + n];
        __nv_bfloat16 wh = __float2bfloat16(w);
        __nv_bfloat16 wl = __float2bfloat16(w - __bfloat162float(wh));
        uint32_t off = (uint32_t)(n * 256 + (((k >> 3) ^ (n & 7)) * 16) + (k & 7) * 2);
        *(__nv_bfloat16*)(hi + off) = wh;
        *(__nv_bfloat16*)(lo + off) = wl;
    }
}

// ---------------------------------------------------------------------------
// Encoder (unchanged)
// ---------------------------------------------------------------------------
__global__ void __launch_bounds__(256) encoder_kernel(
    const float* __restrict__ x, const float* __restrict__ Wenc,
    const float* __restrict__ benc, const float* __restrict__ gamma,
    const float* __restrict__ beta, float* __restrict__ nf_out,
    float* __restrict__ region_out)
{
    const int tid = threadIdx.x;
    const int lane = tid & 31;
    const int w4 = (tid >> 5) & 3;
    const int inst = tid >> 7;
    const long bt = (long)blockIdx.x * 2 + inst;
    const float* xr = x + bt * (R_NODES * 6);
    float* outp = nf_out + bt * NODE_F;
    float* regp = region_out ? region_out + bt * NODE_F : nullptr;

    for (int r = w4; r < R_NODES; r += 4) {
        float xv[6];
#pragma unroll
        for (int c = 0; c < 6; ++c) xv[c] = xr[r * 6 + c];
        float h[4];
#pragma unroll
        for (int j = 0; j < 4; ++j) {
            int k = lane + 32 * j;
            float a = benc[r * HID + k];
#pragma unroll
            for (int c = 0; c < 6; ++c) a = fmaf(xv[c], Wenc[(r * 6 + c) * HID + k], a);
            h[j] = a;
        }
        float s = h[0] + h[1] + h[2] + h[3];
        float sq = h[0]*h[0] + h[1]*h[1] + h[2]*h[2] + h[3]*h[3];
#pragma unroll
        for (int o = 16; o > 0; o >>= 1) {
            s  += __shfl_xor_sync(0xffffffffu, s, o);
            sq += __shfl_xor_sync(0xffffffffu, sq, o);
        }
        float mean = s * (1.0f / 128.0f);
        float var = sq * (1.0f / 128.0f) - mean * mean;
        float rstd = rsqrtf(var + LN_EPS);
#pragma unroll
        for (int j = 0; j < 4; ++j) {
            int k = lane + 32 * j;
            float v = (h[j] - mean) * rstd * gamma[r * HID + k] + beta[r * HID + k];
            float g = gelu_exact(v);
            outp[r * HID + k] = g;
            if (regp) regp[r * HID + k] = g;
        }
    }
}

// ---------------------------------------------------------------------------
// GAT layer, mma.sync bf16 split-3. CTA = 4 instances (40 rows -> 3 m16-tiles,
// rows 40-47 garbage/discarded). 256 threads, 2 CTAs/SM. out in registers.
// smem byte map (112128 total):
//   0       A_hi  (40*256 = 10240; reads may overrun harmlessly)
//   10240   A_lo  (10240)
//   20480   B     (hi 32768 + lo 32768)
//   86016   xp    (40*132*4 = 21120 fp32, stride 132)
//   107136  att   (1024 fp32)
//   111232  als   (40 f)  111392 ald (40 f)  111552 alpha (4*36 f)
// ---------------------------------------------------------------------------
#define A_LO_B   10240
#define B_B      20480
#define XP_B     86016
#define ATT_B    107136
#define ALS_B    111232
#define ALD_B    111392
#define ALPHA_B  111552
#define SM_DYNBYTES 112128

__global__ void __launch_bounds__(256, 2) gat_mma_kernel(
    const float* __restrict__ nf_in, const uint8_t* __restrict__ Wt,
    const float* __restrict__ asrc, const float* __restrict__ adst,
    const float* __restrict__ bg, float* __restrict__ nf_out)
{
    extern __shared__ uint8_t smb[];
    const uint32_t sb = smem_u32(smb);
    float* s_xp    = (float*)(smb + XP_B);
    float* s_att   = (float*)(smb + ATT_B);
    float* s_als   = (float*)(smb + ALS_B);
    float* s_ald   = (float*)(smb + ALD_B);
    float* s_alpha = (float*)(smb + ALPHA_B);

    const int tid  = threadIdx.x;
    const int wid  = tid >> 5;
    const int lane = tid & 31;
    const long blk = blockIdx.x;

    // head-0 B load via cp.async, overlapped with A conversion
    for (int i = tid; i < 4096; i += 256) cpa16(sb + B_B + i * 16, Wt + i * 16);
    asm volatile("cp.async.commit_group;" ::: "memory");

    for (int i = tid; i < 512; i += 256) {
        s_att[i]       = asrc[i];
        s_att[512 + i] = adst[i];
    }

    // A fill: 40 rows x 16 k-chunks = 640 tasks
#pragma unroll
    for (int it = 0; it < 3; ++it) {
        int t = tid + 256 * it;
        if (t < 640) {
            int r = t >> 4, kb = t & 15;
            const float* src = nf_in + (blk * NI + r / R_NODES) * NODE_F + (r % R_NODES) * HID + kb * 8;
            float4 a = *(const float4*)(src);
            float4 b = *(const float4*)(src + 4);
            uint32_t hi[4], lo[4];
            split_bf16x2(a.x, a.y, hi[0], lo[0]);
            split_bf16x2(a.z, a.w, hi[1], lo[1]);
            split_bf16x2(b.x, b.y, hi[2], lo[2]);
            split_bf16x2(b.z, b.w, hi[3], lo[3]);
            uint32_t off = (uint32_t)(r * 256 + ((kb ^ (r & 7)) * 16));
            *(uint4*)(smb + off)          = make_uint4(hi[0], hi[1], hi[2], hi[3]);
            *(uint4*)(smb + A_LO_B + off) = make_uint4(lo[0], lo[1], lo[2], lo[3]);
        }
    }

    // Precompute per-thread agg/epilogue index map (5 float4 tasks per thread)
    int t_rb[5], t_dst[5], t_f[5];
#pragma unroll
    for (int it = 0; it < 5; ++it) {
        int q = tid + 256 * it;               // 0..1279
        int il = q / 320, rem = q - il * 320;
        t_rb[it]  = il * 10;
        t_dst[it] = rem >> 5;
        t_f[it]   = (rem & 31) * 4;
    }
    float4 outacc[5];

    asm volatile("cp.async.wait_group 0;" ::: "memory");
    __syncthreads();

    const uint32_t sA = sb, sB = sb + B_B;

    for (int h = 0; h < 4; ++h) {
        // ---- GEMM: warp owns cols [wid*16, wid*16+16), 3 m-tiles ----
        float acc[3][2][4];
#pragma unroll
        for (int mt = 0; mt < 3; ++mt)
#pragma unroll
            for (int nt = 0; nt < 2; ++nt)
#pragma unroll
                for (int j = 0; j < 4; ++j) acc[mt][nt][j] = 0.f;

#pragma unroll
        for (int kc = 0; kc < 8; ++kc) {
            uint32_t bh[4], bl[4];
            {
                int m = lane >> 3, i = lane & 7;
                int n = wid * 16 + (m >> 1) * 8 + i;
                int kb = kc * 2 + (m & 1);
                uint32_t addr = sB + (uint32_t)(n * 256 + ((kb ^ (n & 7)) * 16));
                ldsm_x4(bh, addr);
                ldsm_x4(bl, addr + 32768);
            }
            {
                int m = lane >> 3, i = lane & 7;
                int kb = kc * 2 + (m >> 1);
                int rbase = (m & 1) * 8 + i;
#pragma unroll
                for (int mt = 0; mt < 3; ++mt) {
                    int r = mt * 16 + rbase;
                    uint32_t addr = sA + (uint32_t)(r * 256 + ((kb ^ (r & 7)) * 16));
                    uint32_t ahi[4], alo[4];
                    ldsm_x4(ahi, addr);
                    ldsm_x4(alo, addr + A_LO_B);
                    mma_bf16(acc[mt][0], ahi, bh[0], bh[1]);
                    mma_bf16(acc[mt][1], ahi, bh[2], bh[3]);
                    mma_bf16(acc[mt][0], alo, bh[0], bh[1]);
                    mma_bf16(acc[mt][1], alo, bh[2], bh[3]);
                    mma_bf16(acc[mt][0], ahi, bl[0], bl[1]);
                    mma_bf16(acc[mt][1], ahi, bl[2], bl[3]);
                }
            }
        }
        // write xp (stride 132); rows >= 40 discarded (mt==2 upper half)
#pragma unroll
        for (int mt = 0; mt < 3; ++mt)
#pragma unroll
            for (int nt = 0; nt < 2; ++nt) {
                int r0 = mt * 16 + (lane >> 2);
                int c  = wid * 16 + nt * 8 + (lane & 3) * 2;
                *(float2*)(s_xp + r0 * 132 + c) = make_float2(acc[mt][nt][0], acc[mt][nt][1]);
                if (mt < 2)
                    *(float2*)(s_xp + (r0 + 8) * 132 + c) = make_float2(acc[mt][nt][2], acc[mt][nt][3]);
            }
        __syncthreads();

        // prefetch next head's B
        if (h < 3) {
            const uint8_t* gsrc = Wt + (size_t)(h + 1) * 65536;
            for (int i = tid; i < 4096; i += 256) cpa16(sb + B_B + i * 16, gsrc + i * 16);
            asm volatile("cp.async.commit_group;" ::: "memory");
        }

        // ---- logits: 40 rows, warp handles 5 ----
#pragma unroll
        for (int rr = 0; rr < 5; ++rr) {
            int r = wid * 5 + rr;
            float as = 0.f, ad = 0.f;
#pragma unroll
            for (int j = 0; j < 4; ++j) {
                float xv = s_xp[r * 132 + lane + 32 * j];
                as = fmaf(xv, s_att[h * 128 + lane + 32 * j], as);
                ad = fmaf(xv, s_att[512 + h * 128 + lane + 32 * j], ad);
            }
#pragma unroll
            for (int o = 16; o > 0; o >>= 1) {
                as += __shfl_xor_sync(0xffffffffu, as, o);
                ad += __shfl_xor_sync(0xffffffffu, ad, o);
            }
            if (lane == 0) { s_als[r] = as; s_ald[r] = ad; }
        }
        __syncthreads();

        // ---- segment softmax ----
        if (tid < 40) {
            int il = tid / 10, dst = tid - il * 10, rb = il * 10;
            float ald = s_ald[rb + dst];
            int s0 = c_start[dst], s1 = c_start[dst + 1];
            float vb[5], m = -1e30f;
            for (int k = s0; k < s1; ++k) {
                float v = s_als[rb + c_src[k]] + ald;
                v = v > 0.f ? v : 0.2f * v;
                vb[k - s0] = v;
                m = fmaxf(m, v);
            }
            float ssum = 0.f;
            for (int k = s0; k < s1; ++k) {
                float ex = expf(vb[k - s0] - m);
                ssum += ex;
                s_alpha[il * NE + k] = ex;
            }
            float inv = 1.0f / ssum;
            for (int k = s0; k < s1; ++k) s_alpha[il * NE + k] *= inv;
        }
        __syncthreads();

        // ---- aggregation into register accumulators ----
#pragma unroll
        for (int it = 0; it < 5; ++it) {
            float4 a4;
            if (h == 0) { a4.x = a4.y = a4.z = a4.w = 0.f; }
            else          a4 = outacc[it];
            const int dst = t_dst[it], rb = t_rb[it], f = t_f[it];
            const int s0 = c_start[dst], s1 = c_start[dst + 1];
            const int ilNE = (rb / 10) * NE;
            for (int k = s0; k < s1; ++k) {
                int row = rb + c_src[k];
                float al = s_alpha[ilNE + k];
                float4 xv = *(const float4*)(s_xp + row * 132 + f);
                a4.x = fmaf(al, xv.x, a4.x);
                a4.y = fmaf(al, xv.y, a4.y);
                a4.z = fmaf(al, xv.z, a4.z);
                a4.w = fmaf(al, xv.w, a4.w);
            }
            outacc[it] = a4;
        }
        if (h < 3) asm volatile("cp.async.wait_group 0;" ::: "memory");
        __syncthreads();
    }

    // ---- epilogue: head mean + bias + GELU + residual ----
#pragma unroll
    for (int it = 0; it < 5; ++it) {
        const int dst = t_dst[it], f = t_f[it];
        const long ig = blk * NI + t_rb[it] / 10;
        float4 o = outacc[it];
        float4 bgv = *(const float4*)(bg + f);
        float4 rs  = *(const float4*)(nf_in + ig * NODE_F + dst * HID + f);
        float4 w;
        w.x = gelu_exact(fmaf(0.25f, o.x, bgv.x)) + rs.x;
        w.y = gelu_exact(fmaf(0.25f, o.y, bgv.y)) + rs.y;
        w.z = gelu_exact(fmaf(0.25f, o.z, bgv.z)) + rs.z;
        w.w = gelu_exact(fmaf(0.25f, o.w, bgv.w)) + rs.w;
        *(float4*)(nf_out + ig * NODE_F + dst * HID + f) = w;
    }
}

// ---------------------------------------------------------------------------
extern "C" void kernel_launch(void* const* d_in, const int* in_sizes, int n_in,
                              void* d_out, int out_size)
{
    const float* x     = (const float*)d_in[0];
    const float* Wenc  = (const float*)d_in[1];
    const float* benc  = (const float*)d_in[2];
    const float* gamma = (const float*)d_in[3];
    const float* beta  = (const float*)d_in[4];
    const float* Wg    = (const float*)d_in[5];
    const float* asrc  = (const float*)d_in[6];
    const float* adst  = (const float*)d_in[7];
    const float* bg    = (const float*)d_in[8];

    float* out = (float*)d_out;
    float* region_out = (out_size >= 2 * NTOT) ? out + NTOT : nullptr;

    float* nf0;  cudaGetSymbolAddress((void**)&nf0, g_nf0);
    float* nf1;  cudaGetSymbolAddress((void**)&nf1, g_nf1);
    uint8_t* wt; cudaGetSymbolAddress((void**)&wt, g_Wt);

    cudaFuncSetAttribute(gat_mma_kernel, cudaFuncAttributeMaxDynamicSharedMemorySize, SM_DYNBYTES);

    wt_kernel<<<12, 256>>>(Wg);
    encoder_kernel<<<BT / 2, 256>>>(x, Wenc, benc, gamma, beta, nf0, region_out);

    gat_mma_kernel<<<GRID_GAT, 256, SM_DYNBYTES>>>(nf0, wt,               asrc,        adst,        bg,       nf1);
    gat_mma_kernel<<<GRID_GAT, 256, SM_DYNBYTES>>>(nf1, wt + 4 * 65536,   asrc + 512,  adst + 512,  bg + 128, nf0);
    gat_mma_kernel<<<GRID_GAT, 256, SM_DYNBYTES>>>(nf0, wt + 8 * 65536,   asrc + 1024, adst + 1024, bg + 256, out);
}

// round 5
// speedup vs baseline: 1.8995x; 1.3182x over previous
#include <cuda_runtime.h>
#include <cuda_bf16.h>
#include <math.h>
#include <stdint.h>

// Problem constants
#define R_NODES 10
#define HID 128
#define NE 36
#define BT 12800
#define NODE_F 1280
#define NTOT (BT * NODE_F)
#define LN_EPS 1e-5f
#define NI 4                            // instances per GAT CTA
#define GRID_GAT (BT / NI)              // 3200

__device__ float g_nf0[NTOT];
__device__ float g_nf1[NTOT];
// W pre-arranged in mma.sync B-fragment layout:
// [layer][head]{ hi: [wid(8)][kc(8)][lane(32)] 16B chunks = 32KB, lo: +32KB }
__device__ __align__(16) uint8_t g_Wt[3 * 4 * 65536];

__constant__ int c_start[R_NODES + 1] = {0, 5, 8, 12, 15, 17, 22, 27, 31, 33, 36};
__constant__ int c_src[NE] = {
    9, 5, 6, 1, 0,   0, 2, 1,   5, 1, 3, 2,   2, 4, 3,   3, 4,
    6, 2, 0, 7, 5,   5, 9, 0, 7, 6,   6, 5, 8, 7,   7, 8,   6, 0, 9
};

__device__ __forceinline__ float gelu_exact(float v) {
    return 0.5f * v * (1.0f + erff(v * 0.70710678118654752440f));
}
__device__ __forceinline__ uint32_t smem_u32(const void* p) {
    uint32_t a;
    asm("{ .reg .u64 t; cvta.to.shared.u64 t, %1; cvt.u32.u64 %0, t; }" : "=r"(a) : "l"(p));
    return a;
}
__device__ __forceinline__ void ldsm_x4(uint32_t* r, uint32_t addr) {
    asm volatile("ldmatrix.sync.aligned.m8n8.x4.shared.b16 {%0,%1,%2,%3}, [%4];"
                 : "=r"(r[0]), "=r"(r[1]), "=r"(r[2]), "=r"(r[3]) : "r"(addr));
}
__device__ __forceinline__ void mma_bf16(float* d, const uint32_t* a, uint32_t b0, uint32_t b1) {
    asm volatile("mma.sync.aligned.m16n8k16.row.col.f32.bf16.bf16.f32 "
                 "{%0,%1,%2,%3}, {%4,%5,%6,%7}, {%8,%9}, {%0,%1,%2,%3};"
                 : "+f"(d[0]), "+f"(d[1]), "+f"(d[2]), "+f"(d[3])
                 : "r"(a[0]), "r"(a[1]), "r"(a[2]), "r"(a[3]), "r"(b0), "r"(b1));
}
__device__ __forceinline__ void split_bf16x2(float v0, float v1, uint32_t& hi, uint32_t& lo) {
    __nv_bfloat16 h0 = __float2bfloat16(v0);
    __nv_bfloat16 h1 = __float2bfloat16(v1);
    __nv_bfloat16 l0 = __float2bfloat16(v0 - __bfloat162float(h0));
    __nv_bfloat16 l1 = __float2bfloat16(v1 - __bfloat162float(h1));
    hi = (uint32_t)__bfloat16_as_ushort(h0) | ((uint32_t)__bfloat16_as_ushort(h1) << 16);
    lo = (uint32_t)__bfloat16_as_ushort(l0) | ((uint32_t)__bfloat16_as_ushort(l1) << 16);
}

// ---------------------------------------------------------------------------
// W prep: Wg (L,128,512) -> per-(warp,kc,lane) B fragments, bf16 hi/lo.
// Fragment chunk c (0..2047): wid=c>>8, kc=(c>>5)&7, lane=c&31.
//   n0 = wid*16 + (lane>>2), k0 = kc*16 + 2*(lane&3)
//   16B = pack(n0,k0 pair), pack(n0,k0+8 pair), pack(n0+8,k0 pair), pack(n0+8,k0+8 pair)
// ---------------------------------------------------------------------------
__global__ void wt_kernel(const float* __restrict__ Wg) {
    int l = blockIdx.x >> 2, h = blockIdx.x & 3;
    uint8_t* base = g_Wt + (size_t)(l * 4 + h) * 65536;
    const float* W = Wg + l * 65536 + h * 128;   // W[k*512 + n]
    for (int c = threadIdx.x; c < 2048; c += 256) {
        int wt_ = c >> 8, kc = (c >> 5) & 7, lane = c & 31;
        int n0 = wt_ * 16 + (lane >> 2);
        int k0 = kc * 16 + 2 * (lane & 3);
        uint32_t hi[4], lo[4];
#pragma unroll
        for (int j = 0; j < 4; ++j) {
            int n = n0 + (j >> 1) * 8;
            int k = k0 + (j & 1) * 8;
            float w0 = W[k * 512 + n];
            float w1 = W[(k + 1) * 512 + n];
            split_bf16x2(w0, w1, hi[j], lo[j]);
        }
        *(uint4*)(base + c * 16)         = make_uint4(hi[0], hi[1], hi[2], hi[3]);
        *(uint4*)(base + 32768 + c * 16) = make_uint4(lo[0], lo[1], lo[2], lo[3]);
    }
}

// ---------------------------------------------------------------------------
// Encoder (unchanged)
// ---------------------------------------------------------------------------
__global__ void __launch_bounds__(256) encoder_kernel(
    const float* __restrict__ x, const float* __restrict__ Wenc,
    const float* __restrict__ benc, const float* __restrict__ gamma,
    const float* __restrict__ beta, float* __restrict__ nf_out,
    float* __restrict__ region_out)
{
    const int tid = threadIdx.x;
    const int lane = tid & 31;
    const int w4 = (tid >> 5) & 3;
    const int inst = tid >> 7;
    const long bt = (long)blockIdx.x * 2 + inst;
    const float* xr = x + bt * (R_NODES * 6);
    float* outp = nf_out + bt * NODE_F;
    float* regp = region_out ? region_out + bt * NODE_F : nullptr;

    for (int r = w4; r < R_NODES; r += 4) {
        float xv[6];
#pragma unroll
        for (int c = 0; c < 6; ++c) xv[c] = xr[r * 6 + c];
        float h[4];
#pragma unroll
        for (int j = 0; j < 4; ++j) {
            int k = lane + 32 * j;
            float a = benc[r * HID + k];
#pragma unroll
            for (int c = 0; c < 6; ++c) a = fmaf(xv[c], Wenc[(r * 6 + c) * HID + k], a);
            h[j] = a;
        }
        float s = h[0] + h[1] + h[2] + h[3];
        float sq = h[0]*h[0] + h[1]*h[1] + h[2]*h[2] + h[3]*h[3];
#pragma unroll
        for (int o = 16; o > 0; o >>= 1) {
            s  += __shfl_xor_sync(0xffffffffu, s, o);
            sq += __shfl_xor_sync(0xffffffffu, sq, o);
        }
        float mean = s * (1.0f / 128.0f);
        float var = sq * (1.0f / 128.0f) - mean * mean;
        float rstd = rsqrtf(var + LN_EPS);
#pragma unroll
        for (int j = 0; j < 4; ++j) {
            int k = lane + 32 * j;
            float v = (h[j] - mean) * rstd * gamma[r * HID + k] + beta[r * HID + k];
            float g = gelu_exact(v);
            outp[r * HID + k] = g;
            if (regp) regp[r * HID + k] = g;
        }
    }
}

// ---------------------------------------------------------------------------
// GAT layer, bf16 split-3 mma.sync, B fragments streamed from L2 via LDG.128.
// CTA = 4 instances (40 rows, 3 m16-tiles), 256 threads, 3 CTAs/SM.
// Per head: GEMM (+xp store, +logit partials from regs) -> sync ->
//           softmax (40 thr) -> sync -> aggregation (s_out RMW) -> sync.
// smem byte map (69376 total):
//   0      A_hi  (10240)       10240  A_lo  (10240)
//   20480  xp    (40*132*4 = 21120)
//   41600  out   (40*128*4 = 20480)
//   62080  att   (4096)
//   66176  alsp  (8*40*4 = 1280)    67456  aldp (1280)
//   68736  alpha (4*36*4 = 576)
// ---------------------------------------------------------------------------
#define A_LO_B   10240
#define XP_B     20480
#define OUT_B    41600
#define ATT_B    62080
#define ALSP_B   66176
#define ALDP_B   67456
#define ALPHA_B  68736
#define SM_DYNBYTES 69376

__global__ void __launch_bounds__(256, 3) gat_mma_kernel(
    const float* __restrict__ nf_in, const uint8_t* __restrict__ Wt,
    const float* __restrict__ asrc, const float* __restrict__ adst,
    const float* __restrict__ bg, float* __restrict__ nf_out)
{
    extern __shared__ uint8_t smb[];
    const uint32_t sb = smem_u32(smb);
    float* s_xp    = (float*)(smb + XP_B);
    float* s_out   = (float*)(smb + OUT_B);
    float* s_att   = (float*)(smb + ATT_B);
    float* s_alsp  = (float*)(smb + ALSP_B);
    float* s_aldp  = (float*)(smb + ALDP_B);
    float* s_alpha = (float*)(smb + ALPHA_B);

    const int tid  = threadIdx.x;
    const int wid  = tid >> 5;
    const int lane = tid & 31;
    const long blk = blockIdx.x;

    for (int i = tid; i < 512; i += 256) {
        s_att[i]       = asrc[i];
        s_att[512 + i] = adst[i];
    }

    // A fill: 40 rows x 16 k-chunks = 640 tasks -> bf16 hi/lo swizzled
#pragma unroll
    for (int it = 0; it < 3; ++it) {
        int t = tid + 256 * it;
        if (t < 640) {
            int r = t >> 4, kb = t & 15;
            const float* src = nf_in + (blk * NI + r / R_NODES) * NODE_F + (r % R_NODES) * HID + kb * 8;
            float4 a = *(const float4*)(src);
            float4 b = *(const float4*)(src + 4);
            uint32_t hi[4], lo[4];
            split_bf16x2(a.x, a.y, hi[0], lo[0]);
            split_bf16x2(a.z, a.w, hi[1], lo[1]);
            split_bf16x2(b.x, b.y, hi[2], lo[2]);
            split_bf16x2(b.z, b.w, hi[3], lo[3]);
            uint32_t off = (uint32_t)(r * 256 + ((kb ^ (r & 7)) * 16));
            *(uint4*)(smb + off)          = make_uint4(hi[0], hi[1], hi[2], hi[3]);
            *(uint4*)(smb + A_LO_B + off) = make_uint4(lo[0], lo[1], lo[2], lo[3]);
        }
    }
    __syncthreads();

    // Per-warp/lane B fragment pointer (uint4 index)
    const uint4* Bp = (const uint4*)Wt + (wid * 256 + lane);

    const int q4 = lane >> 2;               // 0..7
    const int c2 = (lane & 3) * 2;
    const int cbase = wid * 16 + c2;

    for (int h = 0; h < 4; ++h) {
        const uint4* Bh = Bp + h * 4096;

        // ---- GEMM: warp owns cols [wid*16, wid*16+16), 3 m-tiles ----
        float acc[3][2][4];
#pragma unroll
        for (int mt = 0; mt < 3; ++mt)
#pragma unroll
            for (int nt = 0; nt < 2; ++nt)
#pragma unroll
                for (int j = 0; j < 4; ++j) acc[mt][nt][j] = 0.f;

#pragma unroll
        for (int kc = 0; kc < 8; ++kc) {
            uint4 bh = Bh[kc * 32];           // hi fragment (L2-resident)
            uint4 bl = Bh[kc * 32 + 2048];    // lo fragment
            int m = lane >> 3, i2 = lane & 7;
            int kb = kc * 2 + (m >> 1);
            int rbase = (m & 1) * 8 + i2;
#pragma unroll
            for (int mt = 0; mt < 3; ++mt) {
                int r = mt * 16 + rbase;
                uint32_t addr = sb + (uint32_t)(r * 256 + ((kb ^ (r & 7)) * 16));
                uint32_t ahi[4], alo[4];
                ldsm_x4(ahi, addr);
                ldsm_x4(alo, addr + A_LO_B);
                mma_bf16(acc[mt][0], ahi, bh.x, bh.y);
                mma_bf16(acc[mt][1], ahi, bh.z, bh.w);
                mma_bf16(acc[mt][0], alo, bh.x, bh.y);
                mma_bf16(acc[mt][1], alo, bh.z, bh.w);
                mma_bf16(acc[mt][0], ahi, bl.x, bl.y);
                mma_bf16(acc[mt][1], ahi, bl.z, bl.w);
            }
        }

        // ---- xp store + logit partials straight from accumulators ----
        float pals[6], pald[6];
#pragma unroll
        for (int j = 0; j < 6; ++j) { pals[j] = 0.f; pald[j] = 0.f; }
#pragma unroll
        for (int mt = 0; mt < 3; ++mt) {
#pragma unroll
            for (int nt = 0; nt < 2; ++nt) {
                int cc = cbase + nt * 8;
                float a0 = s_att[h * 128 + cc],       a1 = s_att[h * 128 + cc + 1];
                float d0 = s_att[512 + h * 128 + cc], d1 = s_att[512 + h * 128 + cc + 1];
                pals[mt*2]   = fmaf(acc[mt][nt][0], a0, fmaf(acc[mt][nt][1], a1, pals[mt*2]));
                pald[mt*2]   = fmaf(acc[mt][nt][0], d0, fmaf(acc[mt][nt][1], d1, pald[mt*2]));
                pals[mt*2+1] = fmaf(acc[mt][nt][2], a0, fmaf(acc[mt][nt][3], a1, pals[mt*2+1]));
                pald[mt*2+1] = fmaf(acc[mt][nt][2], d0, fmaf(acc[mt][nt][3], d1, pald[mt*2+1]));
                int r0 = mt * 16 + q4;
                *(float2*)(s_xp + r0 * 132 + cc) = make_float2(acc[mt][nt][0], acc[mt][nt][1]);
                if (mt < 2)
                    *(float2*)(s_xp + (r0 + 8) * 132 + cc) = make_float2(acc[mt][nt][2], acc[mt][nt][3]);
            }
        }
        // quad-reduce partials (sum over the warp's 16 cols)
#pragma unroll
        for (int j = 0; j < 6; ++j) {
            pals[j] += __shfl_xor_sync(0xffffffffu, pals[j], 1);
            pals[j] += __shfl_xor_sync(0xffffffffu, pals[j], 2);
            pald[j] += __shfl_xor_sync(0xffffffffu, pald[j], 1);
            pald[j] += __shfl_xor_sync(0xffffffffu, pald[j], 2);
        }
        if ((lane & 3) == 0) {
#pragma unroll
            for (int mt = 0; mt < 3; ++mt) {
                int r0 = mt * 16 + q4;
                s_alsp[wid * 40 + r0] = pals[mt * 2];
                s_aldp[wid * 40 + r0] = pald[mt * 2];
                if (mt < 2) {
                    s_alsp[wid * 40 + r0 + 8] = pals[mt * 2 + 1];
                    s_aldp[wid * 40 + r0 + 8] = pald[mt * 2 + 1];
                }
            }
        }
        __syncthreads();

        // ---- segment softmax (40 workers; reduce 8 warp-partials inline) ----
        if (tid < 40) {
            int il = tid / 10, dst = tid - il * 10, rb = il * 10;
            float ald = 0.f;
#pragma unroll
            for (int w = 0; w < 8; ++w) ald += s_aldp[w * 40 + rb + dst];
            int s0 = c_start[dst], s1 = c_start[dst + 1];
            float vb[5], m = -1e30f;
            for (int k = s0; k < s1; ++k) {
                float als = 0.f;
#pragma unroll
                for (int w = 0; w < 8; ++w) als += s_alsp[w * 40 + rb + c_src[k]];
                float v = als + ald;
                v = v > 0.f ? v : 0.2f * v;
                vb[k - s0] = v;
                m = fmaxf(m, v);
            }
            float ssum = 0.f;
            for (int k = s0; k < s1; ++k) {
                float ex = __expf(vb[k - s0] - m);
                ssum += ex;
                s_alpha[il * NE + k] = ex;
            }
            float inv = 1.0f / ssum;
            for (int k = s0; k < s1; ++k) s_alpha[il * NE + k] *= inv;
        }
        __syncthreads();

        // ---- aggregation (accumulate in s_out) ----
#pragma unroll
        for (int it = 0; it < 5; ++it) {
            int q = tid + 256 * it;                 // 1280 float4 tasks
            int il = q / 320, rem = q - il * 320, dst = rem >> 5, f = (rem & 31) * 4;
            float4 a4;
            if (h == 0) { a4.x = a4.y = a4.z = a4.w = 0.f; }
            else          a4 = ((float4*)s_out)[q];
            int s0 = c_start[dst], s1 = c_start[dst + 1];
            int rb = il * 10;
            for (int k = s0; k < s1; ++k) {
                int row = rb + c_src[k];
                float al = s_alpha[il * NE + k];
                float4 xv = *(const float4*)(s_xp + row * 132 + f);
                a4.x = fmaf(al, xv.x, a4.x);
                a4.y = fmaf(al, xv.y, a4.y);
                a4.z = fmaf(al, xv.z, a4.z);
                a4.w = fmaf(al, xv.w, a4.w);
            }
            ((float4*)s_out)[q] = a4;
        }
        __syncthreads();
    }

    // ---- epilogue: head mean + bias + GELU + residual ----
#pragma unroll
    for (int it = 0; it < 5; ++it) {
        int q = tid + 256 * it;
        int il = q / 320, rem = q - il * 320, dst = rem >> 5, f = (rem & 31) * 4;
        long ig = blk * NI + il;
        float4 o = ((float4*)s_out)[q];
        float4 bgv = *(const float4*)(bg + f);
        float4 rs  = *(const float4*)(nf_in + ig * NODE_F + dst * HID + f);
        float4 w;
        w.x = gelu_exact(fmaf(0.25f, o.x, bgv.x)) + rs.x;
        w.y = gelu_exact(fmaf(0.25f, o.y, bgv.y)) + rs.y;
        w.z = gelu_exact(fmaf(0.25f, o.z, bgv.z)) + rs.z;
        w.w = gelu_exact(fmaf(0.25f, o.w, bgv.w)) + rs.w;
        *(float4*)(nf_out + ig * NODE_F + dst * HID + f) = w;
    }
}

// ---------------------------------------------------------------------------
extern "C" void kernel_launch(void* const* d_in, const int* in_sizes, int n_in,
                              void* d_out, int out_size)
{
    const float* x     = (const float*)d_in[0];
    const float* Wenc  = (const float*)d_in[1];
    const float* benc  = (const float*)d_in[2];
    const float* gamma = (const float*)d_in[3];
    const float* beta  = (const float*)d_in[4];
    const float* Wg    = (const float*)d_in[5];
    const float* asrc  = (const float*)d_in[6];
    const float* adst  = (const float*)d_in[7];
    const float* bg    = (const float*)d_in[8];

    float* out = (float*)d_out;
    float* region_out = (out_size >= 2 * NTOT) ? out + NTOT : nullptr;

    float* nf0;  cudaGetSymbolAddress((void**)&nf0, g_nf0);
    float* nf1;  cudaGetSymbolAddress((void**)&nf1, g_nf1);
    uint8_t* wt; cudaGetSymbolAddress((void**)&wt, g_Wt);

    cudaFuncSetAttribute(gat_mma_kernel, cudaFuncAttributeMaxDynamicSharedMemorySize, SM_DYNBYTES);

    wt_kernel<<<12, 256>>>(Wg);
    encoder_kernel<<<BT / 2, 256>>>(x, Wenc, benc, gamma, beta, nf0, region_out);

    gat_mma_kernel<<<GRID_GAT, 256, SM_DYNBYTES>>>(nf0, wt,               asrc,        adst,        bg,       nf1);
    gat_mma_kernel<<<GRID_GAT, 256, SM_DYNBYTES>>>(nf1, wt + 4 * 65536,   asrc + 512,  adst + 512,  bg + 128, nf0);
    gat_mma_kernel<<<GRID_GAT, 256, SM_DYNBYTES>>>(nf0, wt + 8 * 65536,   asrc + 1024, adst + 1024, bg + 256, out);
}